// round 15
// baseline (speedup 1.0000x reference)
#include <cuda_runtime.h>
#include <cuda_bf16.h>

#define BB 4
#define NN 2048
#define PARAM_G 0.125f
#define VIRUS_DEATH 8e-05f
#define NCHUNK 128              // row-chunks for colsum partials (16 rows each)

// Scratch (allocation-free rule: __device__ globals). All fully overwritten
// each replay -> no zeroing, no atomics, deterministic.
__device__ float g_part[NCHUNK * BB * NN];   // colsum partials [chunk][b][j], 4 MB
__device__ float g_colsum[BB * NN];
__device__ float g_faip[32];                 // per-reduce-CTA fai partials
__device__ float g_taup[32];                 // per-reduce-CTA tau partials

// ---------------------------------------------------------------------------
// Kernel 1: colsum partials. g_part[c][b][j] = sum over 16 rows of chunk c
// of mob[b][i][j] (diagonal zeroed). Thread = 4 columns (float4), 1024 CTAs.
// Emits PDL trigger so the reduce kernel can launch at the earliest point.
// ---------------------------------------------------------------------------
__global__ void __launch_bounds__(256) colsum_part_kernel(const float* __restrict__ mob) {
    const int t  = threadIdx.x;
    const int c4 = blockIdx.x * 256 + t;          // float4 column group
    const int j0 = c4 * 4;
    const int b  = blockIdx.z;
    const int ch = blockIdx.y;
    const int i0 = ch * (NN / NCHUNK);
    const float4* base = (const float4*)(mob + (size_t)b * NN * NN) + c4;
    float4 s = make_float4(0.f, 0.f, 0.f, 0.f);
#pragma unroll 8
    for (int i = i0; i < i0 + NN / NCHUNK; ++i) {
        float4 v = base[(size_t)i * (NN / 4)];
        if (i == j0)     v.x = 0.0f;
        if (i == j0 + 1) v.y = 0.0f;
        if (i == j0 + 2) v.z = 0.0f;
        if (i == j0 + 3) v.w = 0.0f;
        s.x += v.x; s.y += v.y; s.z += v.z; s.w += v.w;
    }
    ((float4*)g_part)[((ch * BB + b) * NN) / 4 + c4] = s;

    cudaTriggerProgrammaticLaunchCompletion();
}

// ---------------------------------------------------------------------------
// Kernel 2: fold partials -> g_colsum[b][j]; per-CTA fai/tau partials.
// Independent SIR read BEFORE the grid sync (overlaps colsum_part tail).
// Grid 32 CTAs: blockIdx.x = b*8 + colblock (256 cols per CTA, thread=1 col).
// ---------------------------------------------------------------------------
__global__ void __launch_bounds__(256) colsum_reduce_kernel(const float* __restrict__ SIR) {
    const int b  = blockIdx.x >> 3;
    const int j  = (blockIdx.x & 7) * 256 + threadIdx.x;

    // Independent of predecessor: harness input read
    const float4 sir = ((const float4*)SIR)[b * NN + j];
    float tau = sir.x + sir.y + sir.z;

    cudaGridDependencySynchronize();   // now wait for g_part

    float s = 0.0f;
#pragma unroll
    for (int c = 0; c < NCHUNK; ++c)
        s += g_part[(c * BB + b) * NN + j];
    g_colsum[b * NN + j] = s;

#pragma unroll
    for (int o = 16; o; o >>= 1) {
        s   += __shfl_down_sync(0xFFFFFFFFu, s, o);
        tau += __shfl_down_sync(0xFFFFFFFFu, tau, o);
    }
    __shared__ float shF[8], shT[8];
    const int w = threadIdx.x >> 5, l = threadIdx.x & 31;
    if (l == 0) { shF[w] = s; shT[w] = tau; }
    __syncthreads();
    if (threadIdx.x == 0) {
        float F = 0.0f, T = 0.0f;
#pragma unroll
        for (int k = 0; k < 8; ++k) { F += shF[k]; T += shT[k]; }
        g_faip[blockIdx.x] = F;
        g_taup[blockIdx.x] = T;
    }
    cudaTriggerProgrammaticLaunchCompletion();
}

// ---------------------------------------------------------------------------
// Kernel 3: main streaming pass — R12 loop body byte-identical (proven).
// Prologue reordered for PDL: SIR->smem staging (independent) runs BEFORE
// the grid sync; faip/colsum reads (dependent) after it.
// Output: [Ht_SIR (B*N*6)] [arrive1 (B*N*4)] [arrive2 (B*N*N*2)]
// ---------------------------------------------------------------------------
__global__ void __launch_bounds__(256) main_kernel(
    const float* __restrict__ param_b, const float* __restrict__ contact,
    const float* __restrict__ mob, const float* __restrict__ SIR,
    const float* __restrict__ sps, const float* __restrict__ birth,
    const float* __restrict__ death, float* __restrict__ out)
{
    __shared__ float sS[NN], sI[NN], sR[NN];   // 24 KB
    __shared__ float sh_m;

    const int b = blockIdx.y;
    const int t = threadIdx.x;

    // Independent of predecessors: stage SIR into SoA smem
    const float4* sir4 = (const float4*)(SIR + (size_t)b * NN * 4);
    for (int j = t; j < NN; j += 256) {
        float4 s = sir4[j];
        sS[j] = s.x; sI[j] = s.y; sR[j] = s.z;
    }

    cudaGridDependencySynchronize();   // wait for reduce outputs

    if (t < 32) {
        float F = (t < 8) ? g_faip[b * 8 + t] : 0.0f;
        float T = (t < 8) ? g_taup[b * 8 + t] : 0.0f;
#pragma unroll
        for (int o = 4; o; o >>= 1) {
            F += __shfl_down_sync(0xFFFFFFFFu, F, o);
            T += __shfl_down_sync(0xFFFFFFFFu, T, o);
        }
        if (t == 0) sh_m = F / T;
    }
    __syncthreads();

    const int wid  = t >> 5;
    const int lane = t & 31;
    const int i    = blockIdx.x * 8 + wid;

    const float rcs = 1.0f / g_colsum[b * NN + i];

    const float4* mobr = (const float4*)(mob + ((size_t)b * NN + i) * NN);
    const float4* spsr = (const float4*)(sps + ((size_t)b * NN + i) * NN);
    const float4* sS4  = (const float4*)sS;
    const float4* sI4  = (const float4*)sI;
    const float4* sR4  = (const float4*)sR;
    const size_t OFF2 = (size_t)BB * NN * 6 + (size_t)BB * NN * 4;
    float4* out2 = (float4*)(out + OFF2 + ((size_t)b * NN + i) * (size_t)NN * 2);

    float fS = 0.0f, fI = 0.0f, fR = 0.0f;

#pragma unroll 4
    for (int k = lane; k < NN / 4; k += 32) {
        float4 f  = mobr[k];            // default policy: keep mob L2-warm
        float4 sp = __ldcs(&spsr[k]);   // streamed once -> evict-first
        const int j0 = k * 4;
        if (j0     == i) { f.x = 0.0f; sp.x = 0.0f; }
        if (j0 + 1 == i) { f.y = 0.0f; sp.y = 0.0f; }
        if (j0 + 2 == i) { f.z = 0.0f; sp.z = 0.0f; }
        if (j0 + 3 == i) { f.w = 0.0f; sp.w = 0.0f; }

        const float4 vS = sS4[k];
        const float4 vI = sI4[k];
        const float4 vR = sR4[k];

        fS += f.x * vS.x + f.y * vS.y + f.z * vS.z + f.w * vS.w;
        fI += f.x * vI.x + f.y * vI.y + f.z * vI.z + f.w * vI.w;
        fR += f.x * vR.x + f.y * vR.y + f.z * vR.z + f.w * vR.w;

        __stcs(&out2[2 * k],     make_float4(sp.x, f.x * rcs, sp.y, f.y * rcs));
        __stcs(&out2[2 * k + 1], make_float4(sp.z, f.z * rcs, sp.w, f.w * rcs));
    }

#pragma unroll
    for (int o = 16; o; o >>= 1) {
        fS += __shfl_down_sync(0xFFFFFFFFu, fS, o);
        fI += __shfl_down_sync(0xFFFFFFFFu, fI, o);
        fR += __shfl_down_sync(0xFFFFFFFFu, fR, o);
    }

    if (lane == 0) {
        const float m_b = sh_m;
        const float S = sS[i], I = sI[i], R = sR[i];
        const float Isum = SIR[((size_t)b * NN + i) * 4 + 3];
        const float pop = S + I + R;
        const float pb  = param_b[b * NN + i];
        const float ct  = contact[b * NN + i];
        const float dth = death[i];
        const float brt = birth[i];

        const float fluxS = m_b * rcs * fS;
        const float fluxI = m_b * rcs * fI;
        const float fluxR = m_b * rcs * fR;

        const float I_new  = S / pop * pb * ct * I;
        const float R_t    = R + PARAM_G * I - dth * R - m_b * R + fluxR;
        const float I_t    = I + I_new - dth * I - PARAM_G * I - VIRUS_DEATH * I - m_b * I + fluxI;
        const float S_t    = S - I_new - dth * S + brt * pop - m_b * S + fluxS;
        const float Isum_t = Isum + I_new;
        const float R0     = pb * ct / (dth + PARAM_G + VIRUS_DEATH + m_b);
        const float W      = pb * ct - dth - PARAM_G - VIRUS_DEATH;

        float* ht = out + (size_t)(b * NN + i) * 6;
        ht[0] = R0;  ht[1] = I_new; ht[2] = S_t;
        ht[3] = I_t; ht[4] = R_t;   ht[5] = Isum_t;

        float* a1 = out + (size_t)BB * NN * 6 + (size_t)(b * NN + i) * 4;
        a1[0] = W; a1[1] = m_b; a1[2] = I; a1[3] = pop;
    }
}

// ---------------------------------------------------------------------------
// Helper: launch with PDL (programmatic stream serialization) enabled.
// ---------------------------------------------------------------------------
template <typename... Args>
static void launch_pdl(void (*kern)(Args...), dim3 grid, dim3 block,
                       Args... args) {
    cudaLaunchConfig_t cfg = {};
    cfg.gridDim = grid;
    cfg.blockDim = block;
    cfg.dynamicSmemBytes = 0;
    cfg.stream = 0;
    cudaLaunchAttribute attr[1];
    attr[0].id = cudaLaunchAttributeProgrammaticStreamSerialization;
    attr[0].val.programmaticStreamSerializationAllowed = 1;
    cfg.attrs = attr;
    cfg.numAttrs = 1;
    cudaLaunchKernelEx(&cfg, kern, args...);
}

extern "C" void kernel_launch(void* const* d_in, const int* in_sizes, int n_in,
                              void* d_out, int out_size) {
    const float* param_b = (const float*)d_in[0];
    const float* contact = (const float*)d_in[1];
    const float* mob     = (const float*)d_in[2];
    const float* SIR     = (const float*)d_in[3];
    const float* sps     = (const float*)d_in[4];
    const float* birth   = (const float*)d_in[5];
    const float* death   = (const float*)d_in[6];
    float* out = (float*)d_out;

    colsum_part_kernel<<<dim3(NN / 1024, NCHUNK, BB), 256>>>(mob);
    launch_pdl(colsum_reduce_kernel, dim3(32), dim3(256), SIR);
    launch_pdl(main_kernel, dim3(NN / 8, BB), dim3(256),
               param_b, contact, mob, SIR, sps, birth, death, out);
}